// round 6
// baseline (speedup 1.0000x reference)
#include <cuda_runtime.h>

#define TW 64
#define TH 32
#define NT 256
#define S  80   // unified smem row stride (floats); gray width == S

#define GH 44   /* gray rows, base oy-6; gray cols base ox-8, width 80 */
#define MH 38

#define LD4(p)    (*(const float4*)(p))
#define ST4(p, v) (*(float4*)(p) = (v))

__device__ __forceinline__ int reflect2i(int c) {
    return (c < 0) ? -c : ((c > 511) ? 1022 - c : c);
}

__global__ __launch_bounds__(NT) void canny_edge_kernel(
    const float* __restrict__ x, float* __restrict__ out)
{
    __shared__ __align__(16) float A[GH * S];          // gray -> blur -> nms
    __shared__ __align__(16) float B[GH * S];          // hblur -> magsq -> colmax
    __shared__ __align__(4)  unsigned char C[MH * S];  // NMS neighbor offset byte

    const int tid  = threadIdx.x;
    const int lane = tid & 31;   // column-quad index (cols 4*lane..4*lane+3)
    const int ty8  = tid >> 5;   // 0..7 row group
    const int ox = blockIdx.x * TW;
    const int oy = blockIdx.y * TH;
    const int n  = blockIdx.z;

    const float gk0 = 0.054488685f;
    const float gk1 = 0.244201342f;
    const float gk2 = 0.402619947f;

    const float* c0 = x + ((size_t)n * 3 + 0) * 512 * 512;
    const float* c1 = x + ((size_t)n * 3 + 1) * 512 * 512;
    const float* c2 = x + ((size_t)n * 3 + 2) * 512 * 512;

    // gray tile spans cols ox-8 .. ox+71 (80 cols), rows oy-6 .. oy+37
    const bool interior = (ox >= 8) && (ox + 72 <= 512) &&
                          (oy >= 6) && (oy + 38 <= 512);

    const float t1 = 0.41421356237f;  // tan(22.5 deg)
    const float t2 = 2.41421356237f;  // tan(67.5 deg)

    // ---- Stage 1: grayscale into A (cols base ox-8, width 80 = 20 quads) ----
    if (interior) {
        if (lane < 20) {
            const int gbase = (oy - 6) * 512 + (ox - 8) + 4 * lane;
            for (int lr = ty8; lr < GH; lr += 8) {
                int idx = gbase + lr * 512;
                float4 a0 = LD4(c0 + idx);
                float4 a1 = LD4(c1 + idx);
                float4 a2 = LD4(c2 + idx);
                float4 g;
                g.x = 0.299f * a2.x + 0.587f * a1.x + 0.114f * a0.x;
                g.y = 0.299f * a2.y + 0.587f * a1.y + 0.114f * a0.y;
                g.z = 0.299f * a2.z + 0.587f * a1.z + 0.114f * a0.z;
                g.w = 0.299f * a2.w + 0.587f * a1.w + 0.114f * a0.w;
                ST4(&A[lr * S + 4 * lane], g);
            }
        }
    } else {
        if (lane < 20) {
            int gx0 = reflect2i(ox - 8 + 4 * lane);
            int gx1 = reflect2i(ox - 8 + 4 * lane + 1);
            int gx2 = reflect2i(ox - 8 + 4 * lane + 2);
            int gx3 = reflect2i(ox - 8 + 4 * lane + 3);
            for (int lr = ty8; lr < GH; lr += 8) {
                int rb = reflect2i(oy - 6 + lr) * 512;
                float4 g;
                g.x = 0.299f * c2[rb + gx0] + 0.587f * c1[rb + gx0] + 0.114f * c0[rb + gx0];
                g.y = 0.299f * c2[rb + gx1] + 0.587f * c1[rb + gx1] + 0.114f * c0[rb + gx1];
                g.z = 0.299f * c2[rb + gx2] + 0.587f * c1[rb + gx2] + 0.114f * c0[rb + gx2];
                g.w = 0.299f * c2[rb + gx3] + 0.587f * c1[rb + gx3] + 0.114f * c0[rb + gx3];
                ST4(&A[lr * S + 4 * lane], g);
            }
        }
    }
    __syncthreads();

    // ---- Stage 2: horizontal blur -> B (base ox-4, width 72 = 18 quads) ----
    // hblur col lc taps gray local cols lc+2 .. lc+6
    if (lane < 18) {
        for (int lr = ty8; lr < GH; lr += 8) {
            const float* a = &A[lr * S + 4 * lane];
            float4 g0 = LD4(a);
            float4 g1 = LD4(a + 4);
            float4 g2 = LD4(a + 8);
            float4 o;
            o.x = gk0 * (g0.z + g1.z) + gk1 * (g0.w + g1.y) + gk2 * g1.x;
            o.y = gk0 * (g0.w + g1.w) + gk1 * (g1.x + g1.z) + gk2 * g1.y;
            o.z = gk0 * (g1.x + g2.x) + gk1 * (g1.y + g1.w) + gk2 * g1.z;
            o.w = gk0 * (g1.y + g2.y) + gk1 * (g1.z + g2.x) + gk2 * g1.w;
            ST4(&B[lr * S + 4 * lane], o);
        }
    }
    __syncthreads();

    // ---- Stage 3: vertical blur -> A (rows base oy-4, 40 rows; rolling) ----
    if (lane < 18) {
        const int r0 = ty8 * 5;
        const int c = 4 * lane;
        float4 w0 = LD4(&B[(r0 + 0) * S + c]);
        float4 w1 = LD4(&B[(r0 + 1) * S + c]);
        float4 w2 = LD4(&B[(r0 + 2) * S + c]);
        float4 w3 = LD4(&B[(r0 + 3) * S + c]);
        #pragma unroll
        for (int j = 0; j < 5; j++) {
            float4 w4 = LD4(&B[(r0 + j + 4) * S + c]);
            float4 o;
            o.x = gk0 * (w0.x + w4.x) + gk1 * (w1.x + w3.x) + gk2 * w2.x;
            o.y = gk0 * (w0.y + w4.y) + gk1 * (w1.y + w3.y) + gk2 * w2.y;
            o.z = gk0 * (w0.z + w4.z) + gk1 * (w1.z + w3.z) + gk2 * w2.z;
            o.w = gk0 * (w0.w + w4.w) + gk1 * (w1.w + w3.w) + gk2 * w2.w;
            ST4(&A[(r0 + j) * S + c], o);
            w0 = w1; w1 = w2; w2 = w3; w3 = w4;
        }
    }
    __syncthreads();

    // ---- Stage 4: Sobel -> magsq in B (base ox-3, rows oy-3, MH=38), offset byte in C ----
    if (interior) {
        if (lane < 18) {
            const int r0 = ty8 * 5;
            const int cnt = min(5, MH - r0);
            const int c = 4 * lane;
            float4 a0 = LD4(&A[(r0 + 0) * S + c]), b0 = LD4(&A[(r0 + 0) * S + c + 4]);
            float4 a1 = LD4(&A[(r0 + 1) * S + c]), b1 = LD4(&A[(r0 + 1) * S + c + 4]);
            for (int j = 0; j < cnt; j++) {
                float4 a2 = LD4(&A[(r0 + j + 2) * S + c]);
                float4 b2 = LD4(&A[(r0 + j + 2) * S + c + 4]);
                float tp[7] = {a0.x, a0.y, a0.z, a0.w, b0.x, b0.y, b0.z};
                float md[7] = {a1.x, a1.y, a1.z, a1.w, b1.x, b1.y, b1.z};
                float bt[7] = {a2.x, a2.y, a2.z, a2.w, b2.x, b2.y, b2.z};
                float mg[4];
                unsigned int cw = 0;
                #pragma unroll
                for (int k = 0; k < 4; k++) {
                    float sx = 0.125f * (tp[k+2] - tp[k]) + 0.25f * (md[k+2] - md[k]) + 0.125f * (bt[k+2] - bt[k]);
                    float sy = 0.125f * (bt[k] - tp[k]) + 0.25f * (bt[k+1] - tp[k+1]) + 0.125f * (bt[k+2] - tp[k+2]);
                    mg[k] = sx * sx + sy * sy + 1e-6f;
                    float adx = fabsf(sx), ady = fabsf(sy);
                    int off;
                    if (ady <= adx * t1)      off = 1;
                    else if (ady >= adx * t2) off = S;
                    else                      off = ((sx > 0.f) == (sy > 0.f)) ? S + 1 : S - 1;
                    cw |= ((unsigned)off) << (8 * k);
                }
                ST4(&B[(r0 + j) * S + c], make_float4(mg[0], mg[1], mg[2], mg[3]));
                *(unsigned int*)&C[(r0 + j) * S + c] = cw;
                a0 = a1; b0 = b1;
                a1 = a2; b1 = b2;
            }
        }
    } else {
        if (lane < 18) {
            #pragma unroll
            for (int sub = 0; sub < 4; sub++) {
                int lc = 4 * lane + sub;
                int gx = ox - 3 + lc;
                bool cv = (unsigned)gx < 512u;
                int cxm = min(max(gx - 1, 0), 511) - (ox - 4);
                int cx0 = min(max(gx,     0), 511) - (ox - 4);
                int cxp = min(max(gx + 1, 0), 511) - (ox - 4);
                for (int lr = ty8; lr < MH; lr += 8) {
                    int gy = oy - 3 + lr;
                    float m = 0.f;
                    int off = 1;
                    if (cv && (unsigned)gy < 512u) {
                        int cym = min(max(gy - 1, 0), 511) - (oy - 4);
                        int cy0 = gy - (oy - 4);
                        int cyp = min(max(gy + 1, 0), 511) - (oy - 4);
                        float bmm = A[cym * S + cxm], bm0 = A[cym * S + cx0], bmp = A[cym * S + cxp];
                        float b0m = A[cy0 * S + cxm],                         b0p = A[cy0 * S + cxp];
                        float bpm = A[cyp * S + cxm], bp0 = A[cyp * S + cx0], bpp = A[cyp * S + cxp];
                        float sx = 0.125f * (bmp - bmm) + 0.25f * (b0p - b0m) + 0.125f * (bpp - bpm);
                        float sy = 0.125f * (bpm - bmm) + 0.25f * (bp0 - bm0) + 0.125f * (bpp - bmp);
                        m = sx * sx + sy * sy + 1e-6f;
                        float adx = fabsf(sx), ady = fabsf(sy);
                        if (ady <= adx * t1)       off = 1;
                        else if (ady >= adx * t2)  off = S;
                        else                       off = ((sx > 0.f) == (sy > 0.f)) ? S + 1 : S - 1;
                    }
                    B[lr * S + lc] = m;
                    C[lr * S + lc] = (unsigned char)off;
                }
            }
        }
    }
    __syncthreads();

    // ---- Stage 5: NMS -> A (base ox-2, rows oy-2, 36x68; magsq==0 outside self-suppresses) ----
    if (lane < 17) {
        const int c4 = 4 * lane;
        for (int lr = ty8; lr < 36; lr += 8) {
            int mi = (lr + 1) * S + c4;
            float4 v0 = LD4(&B[mi]);
            float4 v1 = LD4(&B[mi + 4]);
            unsigned u0 = *(const unsigned*)&C[mi];
            unsigned u1 = *(const unsigned*)&C[mi + 4];
            float m0 = v0.y, m1 = v0.z, m2 = v0.w, m3 = v1.x;
            int o0 = (u0 >> 8) & 255, o1 = (u0 >> 16) & 255, o2 = (u0 >> 24), o3 = u1 & 255;
            float p0 = B[mi + 1 + o0], q0 = B[mi + 1 - o0];
            float p1 = B[mi + 2 + o1], q1 = B[mi + 2 - o1];
            float p2 = B[mi + 3 + o2], q2 = B[mi + 3 - o2];
            float p3 = B[mi + 4 + o3], q3 = B[mi + 4 - o3];
            float4 o;
            o.x = (m0 > p0 && m0 > q0) ? m0 : 0.f;
            o.y = (m1 > p1 && m1 > q1) ? m1 : 0.f;
            o.z = (m2 > p2 && m2 > q2) ? m2 : 0.f;
            o.w = (m3 > p3 && m3 > q3) ? m3 : 0.f;
            ST4(&A[lr * S + c4], o);
        }
    }
    __syncthreads();

    // ---- Stage 6: vertical 5-max -> B (rows base oy, 32 rows; rolling) ----
    if (lane < 17) {
        const int r0 = ty8 * 4;
        const int c = 4 * lane;
        float4 w0 = LD4(&A[(r0 + 0) * S + c]);
        float4 w1 = LD4(&A[(r0 + 1) * S + c]);
        float4 w2 = LD4(&A[(r0 + 2) * S + c]);
        float4 w3 = LD4(&A[(r0 + 3) * S + c]);
        #pragma unroll
        for (int j = 0; j < 4; j++) {
            float4 w4 = LD4(&A[(r0 + j + 4) * S + c]);
            float4 o;
            o.x = fmaxf(fmaxf(fmaxf(w0.x, w1.x), fmaxf(w2.x, w3.x)), w4.x);
            o.y = fmaxf(fmaxf(fmaxf(w0.y, w1.y), fmaxf(w2.y, w3.y)), w4.y);
            o.z = fmaxf(fmaxf(fmaxf(w0.z, w1.z), fmaxf(w2.z, w3.z)), w4.z);
            o.w = fmaxf(fmaxf(fmaxf(w0.w, w1.w), fmaxf(w2.w, w3.w)), w4.w);
            ST4(&B[(r0 + j) * S + c], o);
            w0 = w1; w1 = w2; w2 = w3; w3 = w4;
        }
    }
    __syncthreads();

    // ---- Stage 7: horizontal 5-max + final sqrt, float4 store ----
    if (lane < 16) {
        const int c = 4 * lane;
        for (int lr = ty8; lr < TH; lr += 8) {
            float4 a = LD4(&B[lr * S + c]);
            float4 b = LD4(&B[lr * S + c + 4]);
            float4 o;
            o.x = sqrtf(fmaxf(fmaxf(fmaxf(a.x, a.y), fmaxf(a.z, a.w)), b.x));
            o.y = sqrtf(fmaxf(fmaxf(fmaxf(a.y, a.z), fmaxf(a.w, b.x)), b.y));
            o.z = sqrtf(fmaxf(fmaxf(fmaxf(a.z, a.w), fmaxf(b.x, b.y)), b.z));
            o.w = sqrtf(fmaxf(fmaxf(fmaxf(a.w, b.x), fmaxf(b.y, b.z)), b.w));
            ST4(&out[((size_t)n * 512 + (oy + lr)) * 512 + (ox + c)], o);
        }
    }
}

extern "C" void kernel_launch(void* const* d_in, const int* in_sizes, int n_in,
                              void* d_out, int out_size)
{
    const float* x = (const float*)d_in[0];
    float* out = (float*)d_out;
    dim3 grid(512 / TW, 512 / TH, 32);
    canny_edge_kernel<<<grid, NT>>>(x, out);
}

// round 8
// speedup vs baseline: 1.0021x; 1.0021x over previous
#include <cuda_runtime.h>

#define TW 64
#define TH 64
#define NT 256
#define SA 76   // stride of A (floats)
#define SB 72   // stride of B (floats)

#define GH 76   /* gray rows, base oy-6; cols base ox-6, width 76 */
#define HBH 76  /* hblur rows, base oy-6; cols base ox-4, width 72 */
#define BH 72   /* blur rows, base oy-4; cols base ox-4, width 72 */
#define MH 70   /* magsq rows, base oy-3; cols base ox-3, width 70 */
#define NH 68   /* nms rows, base oy-2; cols base ox-2, width 68 */

#define LD2(p)      (*(const float2*)(p))
#define ST2(p, v)   (*(float2*)(p) = (v))

__device__ __forceinline__ int reflect2i(int c) {
    return (c < 0) ? -c : ((c > 511) ? 1022 - c : c);
}

__device__ __forceinline__ int decode_off(int k) {
    return (k == 0) ? 1 : ((k == 1) ? SB + 1 : ((k == 2) ? SB : SB - 1));
}

__global__ __launch_bounds__(NT) void canny_edge_kernel(
    const float* __restrict__ x, float* __restrict__ out)
{
    __shared__ __align__(16) float A[GH * SA];   // gray -> blur -> nms   (23104 B)
    __shared__ __align__(16) float B[HBH * SB];  // hblur -> magsq -> colmax (21888 B)

    const int tid = threadIdx.x;
    const int tx2 = tid & 31;   // column-pair index
    const int ty8 = tid >> 5;   // 0..7
    const int ox = blockIdx.x * TW;
    const int oy = blockIdx.y * TH;
    const int n  = blockIdx.z;

    const float gk0 = 0.054488685f;
    const float gk1 = 0.244201342f;
    const float gk2 = 0.402619947f;

    const float* c0 = x + ((size_t)n * 3 + 0) * 512 * 512;
    const float* c1 = x + ((size_t)n * 3 + 1) * 512 * 512;
    const float* c2 = x + ((size_t)n * 3 + 2) * 512 * 512;

    // gray tile: rows oy-6..oy+69, cols ox-6..ox+69
    const bool interior = (ox >= 6) && (ox + 70 <= 512) &&
                          (oy >= 6) && (oy + 70 <= 512);

    const float t1 = 0.41421356237f;  // tan(22.5 deg)
    const float t2 = 2.41421356237f;  // tan(67.5 deg)

    // ---- Stage 1: grayscale into A (76 cols = 38 pairs) ----
    if (interior) {
        for (int lr = ty8; lr < GH; lr += 8) {
            const int rowg = (oy - 6 + lr) * 512 + (ox - 6);
            #pragma unroll 2
            for (int pass = 0; pass < 2; pass++) {
                if (pass == 1 && tx2 >= 6) break;
                int cc = 2 * (tx2 + pass * 32);
                float2 a0 = LD2(c0 + rowg + cc);
                float2 a1 = LD2(c1 + rowg + cc);
                float2 a2 = LD2(c2 + rowg + cc);
                float2 g;
                g.x = 0.299f * a2.x + 0.587f * a1.x + 0.114f * a0.x;
                g.y = 0.299f * a2.y + 0.587f * a1.y + 0.114f * a0.y;
                ST2(&A[lr * SA + cc], g);
            }
        }
    } else {
        #pragma unroll 2
        for (int pass = 0; pass < 2; pass++) {
            if (pass == 1 && tx2 >= 6) break;
            int cc = 2 * (tx2 + pass * 32);
            const int gxa = reflect2i(ox - 6 + cc);
            const int gxb = reflect2i(ox - 6 + cc + 1);
            for (int lr = ty8; lr < GH; lr += 8) {
                int rb = reflect2i(oy - 6 + lr) * 512;
                float2 g;
                g.x = 0.299f * c2[rb + gxa] + 0.587f * c1[rb + gxa] + 0.114f * c0[rb + gxa];
                g.y = 0.299f * c2[rb + gxb] + 0.587f * c1[rb + gxb] + 0.114f * c0[rb + gxb];
                ST2(&A[lr * SA + cc], g);
            }
        }
    }
    __syncthreads();

    // ---- Stage 2: horizontal blur -> B (72 cols = 36 pairs) ----
    for (int lr = ty8; lr < HBH; lr += 8) {
        const float* a = &A[lr * SA];
        #pragma unroll 2
        for (int pass = 0; pass < 2; pass++) {
            if (pass == 1 && tx2 >= 4) break;
            int cc = 2 * (tx2 + pass * 32);
            float2 u = LD2(a + cc);
            float2 v = LD2(a + cc + 2);
            float2 w = LD2(a + cc + 4);
            float2 o;
            o.x = gk0 * (u.x + w.x) + gk1 * (u.y + v.y) + gk2 * v.x;
            o.y = gk0 * (u.y + w.y) + gk1 * (v.x + w.x) + gk2 * v.y;
            ST2(&B[lr * SB + cc], o);
        }
    }
    __syncthreads();

    // ---- Stage 3: vertical blur -> A (72 rows; rolling 9/chunk) ----
    {
        const int r0 = ty8 * 9;
        #pragma unroll 2
        for (int pass = 0; pass < 2; pass++) {
            if (pass == 1 && tx2 >= 4) break;
            int c = 2 * (tx2 + pass * 32);
            float2 w0 = LD2(&B[(r0 + 0) * SB + c]);
            float2 w1 = LD2(&B[(r0 + 1) * SB + c]);
            float2 w2 = LD2(&B[(r0 + 2) * SB + c]);
            float2 w3 = LD2(&B[(r0 + 3) * SB + c]);
            #pragma unroll
            for (int j = 0; j < 9; j++) {
                float2 w4 = LD2(&B[(r0 + j + 4) * SB + c]);
                float2 o;
                o.x = gk0 * (w0.x + w4.x) + gk1 * (w1.x + w3.x) + gk2 * w2.x;
                o.y = gk0 * (w0.y + w4.y) + gk1 * (w1.y + w3.y) + gk2 * w2.y;
                ST2(&A[(r0 + j) * SA + c], o);
                w0 = w1; w1 = w2; w2 = w3; w3 = w4;
            }
        }
    }
    __syncthreads();

    // ---- Stage 4+5: Sobel->magsq->NMS with register-retained direction codes ----
    if (interior) {
        const int r0 = ty8 * 9;
        unsigned cwx0 = 0, cwy0 = 0, cwx1 = 0, cwy1 = 0;
        // Stage 4: magsq -> B (70 cols = 35 pairs), codes kept in registers
        #pragma unroll
        for (int pass = 0; pass < 2; pass++) {
            if (pass == 1 && tx2 >= 3) break;
            int c = 2 * (tx2 + pass * 32);
            float2 a0 = LD2(&A[(r0 + 0) * SA + c]), b0 = LD2(&A[(r0 + 0) * SA + c + 2]);
            float2 a1 = LD2(&A[(r0 + 1) * SA + c]), b1 = LD2(&A[(r0 + 1) * SA + c + 2]);
            unsigned cx = 0, cy = 0;
            #pragma unroll
            for (int j = 0; j < 9; j++) {
                if (r0 + j >= MH) break;
                float2 a2 = LD2(&A[(r0 + j + 2) * SA + c]);
                float2 b2 = LD2(&A[(r0 + j + 2) * SA + c + 2]);
                float sx0 = 0.125f * (b0.x - a0.x) + 0.25f * (b1.x - a1.x) + 0.125f * (b2.x - a2.x);
                float sy0 = 0.125f * (a2.x - a0.x) + 0.25f * (a2.y - a0.y) + 0.125f * (b2.x - b0.x);
                float sx1 = 0.125f * (b0.y - a0.y) + 0.25f * (b1.y - a1.y) + 0.125f * (b2.y - a2.y);
                float sy1 = 0.125f * (a2.y - a0.y) + 0.25f * (b2.x - b0.x) + 0.125f * (b2.y - b0.y);
                float2 m;
                m.x = sx0 * sx0 + sy0 * sy0 + 1e-6f;
                m.y = sx1 * sx1 + sy1 * sy1 + 1e-6f;
                float adx0 = fabsf(sx0), ady0 = fabsf(sy0);
                float adx1 = fabsf(sx1), ady1 = fabsf(sy1);
                int k0, k1;
                if (ady0 <= adx0 * t1)      k0 = 0;
                else if (ady0 >= adx0 * t2) k0 = 2;
                else                        k0 = ((sx0 > 0.f) == (sy0 > 0.f)) ? 1 : 3;
                if (ady1 <= adx1 * t1)      k1 = 0;
                else if (ady1 >= adx1 * t2) k1 = 2;
                else                        k1 = ((sx1 > 0.f) == (sy1 > 0.f)) ? 1 : 3;
                cx |= ((unsigned)k0) << (2 * j);
                cy |= ((unsigned)k1) << (2 * j);
                ST2(&B[(r0 + j) * SB + c], m);
                a0 = a1; b0 = b1;
                a1 = a2; b1 = b2;
            }
            if (pass == 0) { cwx0 = cx; cwy0 = cy; } else { cwx1 = cx; cwy1 = cy; }
        }
        __syncthreads();
        // Stage 5: NMS -> A, same pixel ownership as stage 4
        #pragma unroll
        for (int pass = 0; pass < 2; pass++) {
            if (pass == 1 && tx2 >= 3) break;
            int c = 2 * (tx2 + pass * 32);
            unsigned cx = pass ? cwx1 : cwx0;
            unsigned cy = pass ? cwy1 : cwy0;
            #pragma unroll
            for (int j = 0; j < 9; j++) {
                int r = r0 + j;
                if (r >= MH) break;
                if (r >= 1 && r <= 68) {
                    int bi = r * SB + c;
                    if (c > 0) {
                        int off = decode_off((cx >> (2 * j)) & 3);
                        float m = B[bi];
                        float pp = B[bi + off], qq = B[bi - off];
                        A[(r - 1) * SA + (c - 1)] = (m > pp && m > qq) ? m : 0.f;
                    }
                    if (c + 1 <= 68) {
                        int off = decode_off((cy >> (2 * j)) & 3);
                        float m = B[bi + 1];
                        float pp = B[bi + 1 + off], qq = B[bi + 1 - off];
                        A[(r - 1) * SA + c] = (m > pp && m > qq) ? m : 0.f;
                    }
                }
            }
        }
    } else {
        unsigned cb0 = 0, cb1 = 0, cb2 = 0, cb3 = 0;
        // Stage 4 boundary: clamped Sobel, codes retained per (pass, sub)
        #pragma unroll
        for (int pass = 0; pass < 2; pass++) {
            if (pass == 1 && tx2 >= 3) break;
            #pragma unroll
            for (int sub = 0; sub < 2; sub++) {
                int lc = 2 * (tx2 + pass * 32) + sub;
                int gx = ox - 3 + lc;
                bool cv = (unsigned)gx < 512u;
                int cxm = min(max(gx - 1, 0), 511) - (ox - 4);
                int cx0 = min(max(gx,     0), 511) - (ox - 4);
                int cxp = min(max(gx + 1, 0), 511) - (ox - 4);
                unsigned cc = 0;
                #pragma unroll
                for (int k = 0; k < 9; k++) {
                    int lr = ty8 + 8 * k;
                    if (lr >= MH) break;
                    int gy = oy - 3 + lr;
                    float m = 0.f;
                    int kk = 0;
                    if (cv && (unsigned)gy < 512u) {
                        int cym = min(max(gy - 1, 0), 511) - (oy - 4);
                        int cy0 = gy - (oy - 4);
                        int cyp = min(max(gy + 1, 0), 511) - (oy - 4);
                        float bmm = A[cym * SA + cxm], bm0 = A[cym * SA + cx0], bmp = A[cym * SA + cxp];
                        float b0m = A[cy0 * SA + cxm],                          b0p = A[cy0 * SA + cxp];
                        float bpm = A[cyp * SA + cxm], bp0 = A[cyp * SA + cx0], bpp = A[cyp * SA + cxp];
                        float sx = 0.125f * (bmp - bmm) + 0.25f * (b0p - b0m) + 0.125f * (bpp - bpm);
                        float sy = 0.125f * (bpm - bmm) + 0.25f * (bp0 - bm0) + 0.125f * (bpp - bmp);
                        m = sx * sx + sy * sy + 1e-6f;
                        float adx = fabsf(sx), ady = fabsf(sy);
                        if (ady <= adx * t1)       kk = 0;
                        else if (ady >= adx * t2)  kk = 2;
                        else                       kk = ((sx > 0.f) == (sy > 0.f)) ? 1 : 3;
                    }
                    B[lr * SB + lc] = m;
                    cc |= ((unsigned)kk) << (2 * k);
                }
                int slot = pass * 2 + sub;
                if (slot == 0) cb0 = cc; else if (slot == 1) cb1 = cc;
                else if (slot == 2) cb2 = cc; else cb3 = cc;
            }
        }
        __syncthreads();
        // Stage 5 boundary: NMS with retained codes
        #pragma unroll
        for (int pass = 0; pass < 2; pass++) {
            if (pass == 1 && tx2 >= 3) break;
            #pragma unroll
            for (int sub = 0; sub < 2; sub++) {
                int lc = 2 * (tx2 + pass * 32) + sub;
                if (lc < 1 || lc > 68) continue;
                int slot = pass * 2 + sub;
                unsigned cc = (slot == 0) ? cb0 : ((slot == 1) ? cb1 : ((slot == 2) ? cb2 : cb3));
                #pragma unroll
                for (int k = 0; k < 9; k++) {
                    int r = ty8 + 8 * k;
                    if (r >= MH) break;
                    if (r >= 1 && r <= 68) {
                        int bi = r * SB + lc;
                        int off = decode_off((cc >> (2 * k)) & 3);
                        float m = B[bi];
                        float pp = B[bi + off], qq = B[bi - off];
                        A[(r - 1) * SA + (lc - 1)] = (m > pp && m > qq) ? m : 0.f;
                    }
                }
            }
        }
    }
    __syncthreads();

    // ---- Stage 6: vertical 5-max -> B (64 rows; rolling 8/chunk; 68 cols = 34 pairs) ----
    {
        const int r0 = ty8 * 8;
        #pragma unroll 2
        for (int pass = 0; pass < 2; pass++) {
            if (pass == 1 && tx2 >= 2) break;
            int c = 2 * (tx2 + pass * 32);
            float2 w0 = LD2(&A[(r0 + 0) * SA + c]);
            float2 w1 = LD2(&A[(r0 + 1) * SA + c]);
            float2 w2 = LD2(&A[(r0 + 2) * SA + c]);
            float2 w3 = LD2(&A[(r0 + 3) * SA + c]);
            #pragma unroll
            for (int j = 0; j < 8; j++) {
                float2 w4 = LD2(&A[(r0 + j + 4) * SA + c]);
                float2 o;
                o.x = fmaxf(fmaxf(fmaxf(w0.x, w1.x), fmaxf(w2.x, w3.x)), w4.x);
                o.y = fmaxf(fmaxf(fmaxf(w0.y, w1.y), fmaxf(w2.y, w3.y)), w4.y);
                ST2(&B[(r0 + j) * SB + c], o);
                w0 = w1; w1 = w2; w2 = w3; w3 = w4;
            }
        }
    }
    __syncthreads();

    // ---- Stage 7: horizontal 5-max + final sqrt ----
    for (int lr = ty8; lr < TH; lr += 8) {
        int c = 2 * tx2;
        float2 a = LD2(&B[lr * SB + c]);
        float2 b = LD2(&B[lr * SB + c + 2]);
        float2 d = LD2(&B[lr * SB + c + 4]);
        float2 o;
        o.x = sqrtf(fmaxf(fmaxf(fmaxf(a.x, a.y), fmaxf(b.x, b.y)), d.x));
        o.y = sqrtf(fmaxf(fmaxf(fmaxf(a.y, b.x), fmaxf(b.y, d.x)), d.y));
        ST2(&out[((size_t)n * 512 + (oy + lr)) * 512 + (ox + c)], o);
    }
}

extern "C" void kernel_launch(void* const* d_in, const int* in_sizes, int n_in,
                              void* d_out, int out_size)
{
    const float* x = (const float*)d_in[0];
    float* out = (float*)d_out;
    dim3 grid(512 / TW, 512 / TH, 32);
    canny_edge_kernel<<<grid, NT>>>(x, out);
}

// round 9
// speedup vs baseline: 1.0523x; 1.0500x over previous
#include <cuda_runtime.h>

#define TW 64
#define TH 32
#define NT 256
#define S  80   // unified smem row stride (floats)

#define GW 76   /* gray  cols, base ox-6 */
#define GH 44   /* gray  rows, base oy-6 */
#define HBW 72  /* hblur cols, base ox-4 (rows base oy-6) */
#define HBH 44
#define BW 72   /* blur cols, base ox-4 */
#define MH 38   /* mag  rows, base oy-3; cols base ox-3, width 70 */
#define NH 36   /* nms  rows, base oy-2; cols base ox-2, width 68 */

#define LD2(p)      (*(const float2*)(p))
#define ST2(p, v)   (*(float2*)(p) = (v))

__device__ __forceinline__ int reflect2i(int c) {
    return (c < 0) ? -c : ((c > 511) ? 1022 - c : c);
}

__device__ __forceinline__ int decode_off(int k) {
    return (k == 0) ? 1 : ((k == 1) ? S + 1 : ((k == 2) ? S : S - 1));
}

__global__ __launch_bounds__(NT) void canny_edge_kernel(
    const float* __restrict__ x, float* __restrict__ out)
{
    __shared__ __align__(16) float A[GH * S];   // gray -> blur -> nms
    __shared__ __align__(16) float B[GH * S];   // hblur -> magsq -> colmax

    const int tid = threadIdx.x;
    const int tx2 = tid & 31;   // column-pair index
    const int ty8 = tid >> 5;   // 0..7
    const int ox = blockIdx.x * TW;
    const int oy = blockIdx.y * TH;
    const int n  = blockIdx.z;

    const float gk0 = 0.054488685f;
    const float gk1 = 0.244201342f;
    const float gk2 = 0.402619947f;

    const float* c0 = x + ((size_t)n * 3 + 0) * 512 * 512;
    const float* c1 = x + ((size_t)n * 3 + 1) * 512 * 512;
    const float* c2 = x + ((size_t)n * 3 + 2) * 512 * 512;

    const bool interior = (ox >= 6) && (ox + TW + 6 <= 512) &&
                          (oy >= 6) && (oy + TH + 6 <= 512);

    const float t1 = 0.41421356237f;  // tan(22.5 deg)
    const float t2 = 2.41421356237f;  // tan(67.5 deg)

    // ---- Stage 1: grayscale into A ----
    if (interior) {
        const int gbase = (oy - 6) * 512 + (ox - 6);
        for (int lr = ty8; lr < GH; lr += 8) {
            const int rowg = gbase + lr * 512;
            #pragma unroll 2
            for (int pass = 0; pass < 2; pass++) {
                if (pass == 1 && tx2 >= (GW / 2 - 32)) break;
                int cc = 2 * (tx2 + pass * 32);
                float2 a0 = LD2(c0 + rowg + cc);
                float2 a1 = LD2(c1 + rowg + cc);
                float2 a2 = LD2(c2 + rowg + cc);
                float2 g;
                g.x = 0.299f * a2.x + 0.587f * a1.x + 0.114f * a0.x;
                g.y = 0.299f * a2.y + 0.587f * a1.y + 0.114f * a0.y;
                ST2(&A[lr * S + cc], g);
            }
        }
    } else {
        #pragma unroll 2
        for (int pass = 0; pass < 2; pass++) {
            if (pass == 1 && tx2 >= (GW / 2 - 32)) break;
            int cc = 2 * (tx2 + pass * 32);
            const int gxa = reflect2i(ox - 6 + cc);
            const int gxb = reflect2i(ox - 6 + cc + 1);
            for (int lr = ty8; lr < GH; lr += 8) {
                int rb = reflect2i(oy - 6 + lr) * 512;
                float2 g;
                g.x = 0.299f * c2[rb + gxa] + 0.587f * c1[rb + gxa] + 0.114f * c0[rb + gxa];
                g.y = 0.299f * c2[rb + gxb] + 0.587f * c1[rb + gxb] + 0.114f * c0[rb + gxb];
                ST2(&A[lr * S + cc], g);
            }
        }
    }
    __syncthreads();

    // ---- Stage 2: horizontal blur -> B ----
    for (int lr = ty8; lr < HBH; lr += 8) {
        const float* a = &A[lr * S];
        #pragma unroll 2
        for (int pass = 0; pass < 2; pass++) {
            if (pass == 1 && tx2 >= (HBW / 2 - 32)) break;
            int cc = 2 * (tx2 + pass * 32);
            float2 u = LD2(a + cc);
            float2 v = LD2(a + cc + 2);
            float2 w = LD2(a + cc + 4);
            float2 o;
            o.x = gk0 * (u.x + w.x) + gk1 * (u.y + v.y) + gk2 * v.x;
            o.y = gk0 * (u.y + w.y) + gk1 * (v.x + w.x) + gk2 * v.y;
            ST2(&B[lr * S + cc], o);
        }
    }
    __syncthreads();

    // ---- Stage 3: vertical blur -> A (40 rows; rolling 5/chunk) ----
    {
        const int r0 = ty8 * 5;
        #pragma unroll 2
        for (int pass = 0; pass < 2; pass++) {
            if (pass == 1 && tx2 >= (BW / 2 - 32)) break;
            int c = 2 * (tx2 + pass * 32);
            float2 w0 = LD2(&B[(r0 + 0) * S + c]);
            float2 w1 = LD2(&B[(r0 + 1) * S + c]);
            float2 w2 = LD2(&B[(r0 + 2) * S + c]);
            float2 w3 = LD2(&B[(r0 + 3) * S + c]);
            #pragma unroll
            for (int j = 0; j < 5; j++) {
                float2 w4 = LD2(&B[(r0 + j + 4) * S + c]);
                float2 o;
                o.x = gk0 * (w0.x + w4.x) + gk1 * (w1.x + w3.x) + gk2 * w2.x;
                o.y = gk0 * (w0.y + w4.y) + gk1 * (w1.y + w3.y) + gk2 * w2.y;
                ST2(&A[(r0 + j) * S + c], o);
                w0 = w1; w1 = w2; w2 = w3; w3 = w4;
            }
        }
    }
    __syncthreads();

    // ---- Stage 4: Sobel -> magsq in B; direction codes retained in registers ----
    unsigned cwx0 = 0, cwy0 = 0, cwx1 = 0, cwy1 = 0;   // 2 bits/row, 5 rows
    if (interior) {
        const int r0 = ty8 * 5;
        const int cnt = min(5, MH - r0);
        #pragma unroll
        for (int pass = 0; pass < 2; pass++) {
            if (pass == 1 && tx2 >= 3) break;  // 35 pairs
            int c = 2 * (tx2 + pass * 32);
            float2 a0 = LD2(&A[(r0 + 0) * S + c]), b0 = LD2(&A[(r0 + 0) * S + c + 2]);
            float2 a1 = LD2(&A[(r0 + 1) * S + c]), b1 = LD2(&A[(r0 + 1) * S + c + 2]);
            unsigned cx = 0, cy = 0;
            for (int j = 0; j < cnt; j++) {
                float2 a2 = LD2(&A[(r0 + j + 2) * S + c]);
                float2 b2 = LD2(&A[(r0 + j + 2) * S + c + 2]);
                float sx0 = 0.125f * (b0.x - a0.x) + 0.25f * (b1.x - a1.x) + 0.125f * (b2.x - a2.x);
                float sy0 = 0.125f * (a2.x - a0.x) + 0.25f * (a2.y - a0.y) + 0.125f * (b2.x - b0.x);
                float sx1 = 0.125f * (b0.y - a0.y) + 0.25f * (b1.y - a1.y) + 0.125f * (b2.y - a2.y);
                float sy1 = 0.125f * (a2.y - a0.y) + 0.25f * (b2.x - b0.x) + 0.125f * (b2.y - b0.y);
                float2 m;
                m.x = sx0 * sx0 + sy0 * sy0 + 1e-6f;
                m.y = sx1 * sx1 + sy1 * sy1 + 1e-6f;
                float adx0 = fabsf(sx0), ady0 = fabsf(sy0);
                float adx1 = fabsf(sx1), ady1 = fabsf(sy1);
                int k0, k1;
                if (ady0 <= adx0 * t1)      k0 = 0;
                else if (ady0 >= adx0 * t2) k0 = 2;
                else                        k0 = ((sx0 > 0.f) == (sy0 > 0.f)) ? 1 : 3;
                if (ady1 <= adx1 * t1)      k1 = 0;
                else if (ady1 >= adx1 * t2) k1 = 2;
                else                        k1 = ((sx1 > 0.f) == (sy1 > 0.f)) ? 1 : 3;
                cx |= ((unsigned)k0) << (2 * j);
                cy |= ((unsigned)k1) << (2 * j);
                ST2(&B[(r0 + j) * S + c], m);
                a0 = a1; b0 = b1;
                a1 = a2; b1 = b2;
            }
            if (pass == 0) { cwx0 = cx; cwy0 = cy; } else { cwx1 = cx; cwy1 = cy; }
        }
    } else {
        #pragma unroll
        for (int pass = 0; pass < 2; pass++) {
            if (pass == 1 && tx2 >= 3) break;
            #pragma unroll
            for (int sub = 0; sub < 2; sub++) {
                int lc = 2 * (tx2 + pass * 32) + sub;
                int gx = ox - 3 + lc;
                bool cv = (unsigned)gx < 512u;
                int cxm = min(max(gx - 1, 0), 511) - (ox - 4);
                int cx0 = min(max(gx,     0), 511) - (ox - 4);
                int cxp = min(max(gx + 1, 0), 511) - (ox - 4);
                unsigned cc = 0;
                #pragma unroll
                for (int k = 0; k < 5; k++) {
                    int lr = ty8 + 8 * k;
                    if (lr >= MH) break;
                    int gy = oy - 3 + lr;
                    float m = 0.f;
                    int kk = 0;
                    if (cv && (unsigned)gy < 512u) {
                        int cym = min(max(gy - 1, 0), 511) - (oy - 4);
                        int cy0 = gy - (oy - 4);
                        int cyp = min(max(gy + 1, 0), 511) - (oy - 4);
                        float bmm = A[cym * S + cxm], bm0 = A[cym * S + cx0], bmp = A[cym * S + cxp];
                        float b0m = A[cy0 * S + cxm],                         b0p = A[cy0 * S + cxp];
                        float bpm = A[cyp * S + cxm], bp0 = A[cyp * S + cx0], bpp = A[cyp * S + cxp];
                        float sx = 0.125f * (bmp - bmm) + 0.25f * (b0p - b0m) + 0.125f * (bpp - bpm);
                        float sy = 0.125f * (bpm - bmm) + 0.25f * (bp0 - bm0) + 0.125f * (bpp - bmp);
                        m = sx * sx + sy * sy + 1e-6f;
                        float adx = fabsf(sx), ady = fabsf(sy);
                        if (ady <= adx * t1)       kk = 0;
                        else if (ady >= adx * t2)  kk = 2;
                        else                       kk = ((sx > 0.f) == (sy > 0.f)) ? 1 : 3;
                    }
                    B[lr * S + lc] = m;
                    cc |= ((unsigned)kk) << (2 * k);
                }
                int slot = pass * 2 + sub;
                if (slot == 0) cwx0 = cc; else if (slot == 1) cwy0 = cc;
                else if (slot == 2) cwx1 = cc; else cwy1 = cc;
            }
        }
    }
    __syncthreads();

    // ---- Stage 5: NMS -> A, same ownership as stage 4 (codes from registers) ----
    // NMS for mag (r, mc) writes A[r-1, mc-1]; needs mc in 1..68, r in 1..36.
    if (interior) {
        const int r0 = ty8 * 5;
        #pragma unroll
        for (int pass = 0; pass < 2; pass++) {
            if (pass == 1 && tx2 >= 3) break;
            int c = 2 * (tx2 + pass * 32);
            unsigned cx = pass ? cwx1 : cwx0;
            unsigned cy = pass ? cwy1 : cwy0;
            #pragma unroll
            for (int j = 0; j < 5; j++) {
                int r = r0 + j;
                if (r >= 1 && r <= NH) {
                    int bi = r * S + c;
                    if (c > 0) {
                        int off = decode_off((cx >> (2 * j)) & 3);
                        float m = B[bi];
                        float pp = B[bi + off], qq = B[bi - off];
                        A[(r - 1) * S + (c - 1)] = (m > pp && m > qq) ? m : 0.f;
                    }
                    if (c + 1 <= 68) {
                        int off = decode_off((cy >> (2 * j)) & 3);
                        float m = B[bi + 1];
                        float pp = B[bi + 1 + off], qq = B[bi + 1 - off];
                        A[(r - 1) * S + c] = (m > pp && m > qq) ? m : 0.f;
                    }
                }
            }
        }
    } else {
        #pragma unroll
        for (int pass = 0; pass < 2; pass++) {
            if (pass == 1 && tx2 >= 3) break;
            #pragma unroll
            for (int sub = 0; sub < 2; sub++) {
                int lc = 2 * (tx2 + pass * 32) + sub;
                if (lc < 1 || lc > 68) continue;
                int slot = pass * 2 + sub;
                unsigned cc = (slot == 0) ? cwx0 : ((slot == 1) ? cwy0 : ((slot == 2) ? cwx1 : cwy1));
                #pragma unroll
                for (int k = 0; k < 5; k++) {
                    int r = ty8 + 8 * k;
                    if (r >= 1 && r <= NH && r < MH) {
                        int bi = r * S + lc;
                        int off = decode_off((cc >> (2 * k)) & 3);
                        float m = B[bi];
                        float pp = B[bi + off], qq = B[bi - off];
                        A[(r - 1) * S + (lc - 1)] = (m > pp && m > qq) ? m : 0.f;
                    }
                }
            }
        }
    }
    __syncthreads();

    // ---- Stage 6: vertical 5-max -> B (32 rows; rolling 4/chunk; 68 cols) ----
    {
        const int r0 = ty8 * 4;
        #pragma unroll 2
        for (int pass = 0; pass < 2; pass++) {
            if (pass == 1 && tx2 >= 2) break;  // 34 pairs
            int c = 2 * (tx2 + pass * 32);
            float2 w0 = LD2(&A[(r0 + 0) * S + c]);
            float2 w1 = LD2(&A[(r0 + 1) * S + c]);
            float2 w2 = LD2(&A[(r0 + 2) * S + c]);
            float2 w3 = LD2(&A[(r0 + 3) * S + c]);
            #pragma unroll
            for (int j = 0; j < 4; j++) {
                float2 w4 = LD2(&A[(r0 + j + 4) * S + c]);
                float2 o;
                o.x = fmaxf(fmaxf(fmaxf(w0.x, w1.x), fmaxf(w2.x, w3.x)), w4.x);
                o.y = fmaxf(fmaxf(fmaxf(w0.y, w1.y), fmaxf(w2.y, w3.y)), w4.y);
                ST2(&B[(r0 + j) * S + c], o);
                w0 = w1; w1 = w2; w2 = w3; w3 = w4;
            }
        }
    }
    __syncthreads();

    // ---- Stage 7: horizontal 5-max + final sqrt ----
    for (int lr = ty8; lr < TH; lr += 8) {
        int c = 2 * tx2;
        float2 a = LD2(&B[lr * S + c]);
        float2 b = LD2(&B[lr * S + c + 2]);
        float2 d = LD2(&B[lr * S + c + 4]);
        float2 o;
        o.x = sqrtf(fmaxf(fmaxf(fmaxf(a.x, a.y), fmaxf(b.x, b.y)), d.x));
        o.y = sqrtf(fmaxf(fmaxf(fmaxf(a.y, b.x), fmaxf(b.y, d.x)), d.y));
        ST2(&out[((size_t)n * 512 + (oy + lr)) * 512 + (ox + c)], o);
    }
}

extern "C" void kernel_launch(void* const* d_in, const int* in_sizes, int n_in,
                              void* d_out, int out_size)
{
    const float* x = (const float*)d_in[0];
    float* out = (float*)d_out;
    dim3 grid(512 / TW, 512 / TH, 32);
    canny_edge_kernel<<<grid, NT>>>(x, out);
}

// round 11
// speedup vs baseline: 1.2952x; 1.2308x over previous
#include <cuda_runtime.h>

#define TW 64
#define TH 32
#define NT 320
#define S  80   // unified smem row stride (floats)

#define GH 44   /* gray rows, base oy-6; cols base ox-6, 76 wide (38 pairs) */
#define HBH 44  /* hblur rows, base oy-6; cols base ox-4, 72 wide (36 pairs) */
#define MH 38   /* mag rows, base oy-3; cols base ox-3, 70 wide (35 pairs) */
#define NH 36   /* nms rows, base oy-2; cols base ox-2, 68 wide (34 pairs) */

#define LD2(p)      (*(const float2*)(p))
#define ST2(p, v)   (*(float2*)(p) = (v))

__device__ __forceinline__ int reflect2i(int c) {
    return (c < 0) ? -c : ((c > 511) ? 1022 - c : c);
}

__device__ __forceinline__ int decode_off(int k) {
    return (k == 0) ? 1 : ((k == 1) ? S + 1 : ((k == 2) ? S : S - 1));
}

__global__ __launch_bounds__(NT) void canny_edge_kernel(
    const float* __restrict__ x, float* __restrict__ out)
{
    __shared__ __align__(16) float A[GH * S];   // gray -> blur -> nms
    __shared__ __align__(16) float B[GH * S];   // hblur -> magsq -> colmax

    const int tid = threadIdx.x;
    const int tx = tid % 40;    // pair index 0..39 (covers up to 80 cols)
    const int ty = tid / 40;    // row group 0..7
    const int ox = blockIdx.x * TW;
    const int oy = blockIdx.y * TH;
    const int n  = blockIdx.z;

    const float gk0 = 0.054488685f;
    const float gk1 = 0.244201342f;
    const float gk2 = 0.402619947f;

    const float* c0 = x + ((size_t)n * 3 + 0) * 512 * 512;
    const float* c1 = x + ((size_t)n * 3 + 1) * 512 * 512;
    const float* c2 = x + ((size_t)n * 3 + 2) * 512 * 512;

    const bool interior = (ox >= 6) && (ox + TW + 6 <= 512) &&
                          (oy >= 6) && (oy + TH + 6 <= 512);

    const float t1 = 0.41421356237f;  // tan(22.5 deg)
    const float t2 = 2.41421356237f;  // tan(67.5 deg)

    // ---- Stage 1: grayscale into A (38 pairs) ----
    if (tx < 38) {
        const int cc = 2 * tx;
        if (interior) {
            const int gbase = (oy - 6) * 512 + (ox - 6) + cc;
            for (int lr = ty; lr < GH; lr += 8) {
                const int idx = gbase + lr * 512;
                float2 a0 = LD2(c0 + idx);
                float2 a1 = LD2(c1 + idx);
                float2 a2 = LD2(c2 + idx);
                float2 g;
                g.x = 0.299f * a2.x + 0.587f * a1.x + 0.114f * a0.x;
                g.y = 0.299f * a2.y + 0.587f * a1.y + 0.114f * a0.y;
                ST2(&A[lr * S + cc], g);
            }
        } else {
            const int gxa = reflect2i(ox - 6 + cc);
            const int gxb = reflect2i(ox - 6 + cc + 1);
            for (int lr = ty; lr < GH; lr += 8) {
                int rb = reflect2i(oy - 6 + lr) * 512;
                float2 g;
                g.x = 0.299f * c2[rb + gxa] + 0.587f * c1[rb + gxa] + 0.114f * c0[rb + gxa];
                g.y = 0.299f * c2[rb + gxb] + 0.587f * c1[rb + gxb] + 0.114f * c0[rb + gxb];
                ST2(&A[lr * S + cc], g);
            }
        }
    }
    __syncthreads();

    // ---- Stage 2: horizontal blur -> B (36 pairs) ----
    if (tx < 36) {
        const int cc = 2 * tx;
        for (int lr = ty; lr < HBH; lr += 8) {
            const float* a = &A[lr * S + cc];
            float2 u = LD2(a);
            float2 v = LD2(a + 2);
            float2 w = LD2(a + 4);
            float2 o;
            o.x = gk0 * (u.x + w.x) + gk1 * (u.y + v.y) + gk2 * v.x;
            o.y = gk0 * (u.y + w.y) + gk1 * (v.x + w.x) + gk2 * v.y;
            ST2(&B[lr * S + cc], o);
        }
    }
    __syncthreads();

    // ---- Stage 3: vertical blur -> A (40 rows; rolling 5/chunk; 36 pairs) ----
    if (tx < 36) {
        const int r0 = ty * 5;
        const int c = 2 * tx;
        float2 w0 = LD2(&B[(r0 + 0) * S + c]);
        float2 w1 = LD2(&B[(r0 + 1) * S + c]);
        float2 w2 = LD2(&B[(r0 + 2) * S + c]);
        float2 w3 = LD2(&B[(r0 + 3) * S + c]);
        #pragma unroll
        for (int j = 0; j < 5; j++) {
            float2 w4 = LD2(&B[(r0 + j + 4) * S + c]);
            float2 o;
            o.x = gk0 * (w0.x + w4.x) + gk1 * (w1.x + w3.x) + gk2 * w2.x;
            o.y = gk0 * (w0.y + w4.y) + gk1 * (w1.y + w3.y) + gk2 * w2.y;
            ST2(&A[(r0 + j) * S + c], o);
            w0 = w1; w1 = w2; w2 = w3; w3 = w4;
        }
    }
    __syncthreads();

    // ---- Stage 4: Sobel -> magsq in B (35 pairs); direction codes kept in registers ----
    unsigned cwx = 0, cwy = 0;   // 2 bits per row, up to 5 rows
    if (interior) {
        if (tx < 35) {
            const int r0 = ty * 5;
            const int cnt = min(5, MH - r0);   // ty==7 -> 3
            const int c = 2 * tx;
            float2 a0 = LD2(&A[(r0 + 0) * S + c]), b0 = LD2(&A[(r0 + 0) * S + c + 2]);
            float2 a1 = LD2(&A[(r0 + 1) * S + c]), b1 = LD2(&A[(r0 + 1) * S + c + 2]);
            for (int j = 0; j < cnt; j++) {
                float2 a2 = LD2(&A[(r0 + j + 2) * S + c]);
                float2 b2 = LD2(&A[(r0 + j + 2) * S + c + 2]);
                float sx0 = 0.125f * (b0.x - a0.x) + 0.25f * (b1.x - a1.x) + 0.125f * (b2.x - a2.x);
                float sy0 = 0.125f * (a2.x - a0.x) + 0.25f * (a2.y - a0.y) + 0.125f * (b2.x - b0.x);
                float sx1 = 0.125f * (b0.y - a0.y) + 0.25f * (b1.y - a1.y) + 0.125f * (b2.y - a2.y);
                float sy1 = 0.125f * (a2.y - a0.y) + 0.25f * (b2.x - b0.x) + 0.125f * (b2.y - b0.y);
                float2 m;
                m.x = sx0 * sx0 + sy0 * sy0 + 1e-6f;
                m.y = sx1 * sx1 + sy1 * sy1 + 1e-6f;
                float adx0 = fabsf(sx0), ady0 = fabsf(sy0);
                float adx1 = fabsf(sx1), ady1 = fabsf(sy1);
                int k0, k1;
                if (ady0 <= adx0 * t1)      k0 = 0;
                else if (ady0 >= adx0 * t2) k0 = 2;
                else                        k0 = ((sx0 > 0.f) == (sy0 > 0.f)) ? 1 : 3;
                if (ady1 <= adx1 * t1)      k1 = 0;
                else if (ady1 >= adx1 * t2) k1 = 2;
                else                        k1 = ((sx1 > 0.f) == (sy1 > 0.f)) ? 1 : 3;
                cwx |= ((unsigned)k0) << (2 * j);
                cwy |= ((unsigned)k1) << (2 * j);
                ST2(&B[(r0 + j) * S + c], m);
                a0 = a1; b0 = b1;
                a1 = a2; b1 = b2;
            }
        }
    } else {
        if (tx < 35) {
            #pragma unroll
            for (int sub = 0; sub < 2; sub++) {
                int lc = 2 * tx + sub;
                int gx = ox - 3 + lc;
                bool cv = (unsigned)gx < 512u;
                int cxm = min(max(gx - 1, 0), 511) - (ox - 4);
                int cx0 = min(max(gx,     0), 511) - (ox - 4);
                int cxp = min(max(gx + 1, 0), 511) - (ox - 4);
                unsigned cc = 0;
                #pragma unroll
                for (int k = 0; k < 5; k++) {
                    int lr = ty * 5 + k;
                    if (lr >= MH) break;
                    int gy = oy - 3 + lr;
                    float m = 0.f;
                    int kk = 0;
                    if (cv && (unsigned)gy < 512u) {
                        int cym = min(max(gy - 1, 0), 511) - (oy - 4);
                        int cy0 = gy - (oy - 4);
                        int cyp = min(max(gy + 1, 0), 511) - (oy - 4);
                        float bmm = A[cym * S + cxm], bm0 = A[cym * S + cx0], bmp = A[cym * S + cxp];
                        float b0m = A[cy0 * S + cxm],                         b0p = A[cy0 * S + cxp];
                        float bpm = A[cyp * S + cxm], bp0 = A[cyp * S + cx0], bpp = A[cyp * S + cxp];
                        float sx = 0.125f * (bmp - bmm) + 0.25f * (b0p - b0m) + 0.125f * (bpp - bpm);
                        float sy = 0.125f * (bpm - bmm) + 0.25f * (bp0 - bm0) + 0.125f * (bpp - bmp);
                        m = sx * sx + sy * sy + 1e-6f;
                        float adx = fabsf(sx), ady = fabsf(sy);
                        if (ady <= adx * t1)       kk = 0;
                        else if (ady >= adx * t2)  kk = 2;
                        else                       kk = ((sx > 0.f) == (sy > 0.f)) ? 1 : 3;
                    }
                    B[lr * S + lc] = m;
                    cc |= ((unsigned)kk) << (2 * k);
                }
                if (sub == 0) cwx = cc; else cwy = cc;
            }
        }
    }
    __syncthreads();

    // ---- Stage 5: NMS -> A (ownership matches stage 4; codes from registers) ----
    // mag (r, mc) -> A[r-1, mc-1]; valid mc 1..68, r 1..36.
    if (tx < 35) {
        const int c = 2 * tx;
        const int r0 = ty * 5;
        #pragma unroll
        for (int j = 0; j < 5; j++) {
            int r = r0 + j;
            if (r >= 1 && r <= NH && r < MH) {
                int bi = r * S + c;
                if (c > 0) {
                    int off = decode_off((cwx >> (2 * j)) & 3);
                    float m = B[bi];
                    float pp = B[bi + off], qq = B[bi - off];
                    A[(r - 1) * S + (c - 1)] = (m > pp && m > qq) ? m : 0.f;
                }
                if (c + 1 <= 68) {
                    int off = decode_off((cwy >> (2 * j)) & 3);
                    float m = B[bi + 1];
                    float pp = B[bi + 1 + off], qq = B[bi + 1 - off];
                    A[(r - 1) * S + c] = (m > pp && m > qq) ? m : 0.f;
                }
            }
        }
    }
    __syncthreads();

    // ---- Stage 6: vertical 5-max -> B (32 rows; rolling 4/chunk; 34 pairs) ----
    if (tx < 34) {
        const int r0 = ty * 4;
        const int c = 2 * tx;
        float2 w0 = LD2(&A[(r0 + 0) * S + c]);
        float2 w1 = LD2(&A[(r0 + 1) * S + c]);
        float2 w2 = LD2(&A[(r0 + 2) * S + c]);
        float2 w3 = LD2(&A[(r0 + 3) * S + c]);
        #pragma unroll
        for (int j = 0; j < 4; j++) {
            float2 w4 = LD2(&A[(r0 + j + 4) * S + c]);
            float2 o;
            o.x = fmaxf(fmaxf(fmaxf(w0.x, w1.x), fmaxf(w2.x, w3.x)), w4.x);
            o.y = fmaxf(fmaxf(fmaxf(w0.y, w1.y), fmaxf(w2.y, w3.y)), w4.y);
            ST2(&B[(r0 + j) * S + c], o);
            w0 = w1; w1 = w2; w2 = w3; w3 = w4;
        }
    }
    __syncthreads();

    // ---- Stage 7: horizontal 5-max + final sqrt (32 pairs) ----
    if (tx < 32) {
        const int c = 2 * tx;
        for (int lr = ty; lr < TH; lr += 8) {
            float2 a = LD2(&B[lr * S + c]);
            float2 b = LD2(&B[lr * S + c + 2]);
            float2 d = LD2(&B[lr * S + c + 4]);
            float2 o;
            o.x = sqrtf(fmaxf(fmaxf(fmaxf(a.x, a.y), fmaxf(b.x, b.y)), d.x));
            o.y = sqrtf(fmaxf(fmaxf(fmaxf(a.y, b.x), fmaxf(b.y, d.x)), d.y));
            ST2(&out[((size_t)n * 512 + (oy + lr)) * 512 + (ox + c)], o);
        }
    }
}

extern "C" void kernel_launch(void* const* d_in, const int* in_sizes, int n_in,
                              void* d_out, int out_size)
{
    const float* x = (const float*)d_in[0];
    float* out = (float*)d_out;
    dim3 grid(512 / TW, 512 / TH, 32);
    canny_edge_kernel<<<grid, NT>>>(x, out);
}